// round 1
// baseline (speedup 1.0000x reference)
#include <cuda_runtime.h>
#include <math.h>

#define DIMN 3
#define NPTS 30
#define KK   181
#define PP   24360          // 30*29*28
#define DE   190            // 9 + 181
#define RESTN 27
#define SORT_V 32768        // pow2 >= PP for stage-3 bitonic

// ------------------------- device scratch (static, allowed) -------------------------
__device__ float g_vec[(size_t)PP * DE];        // (P, 190)
__device__ float g_wsT[190 * 192];              // Ws_out transposed, padded cols->192
__device__ float g_sm2T[(size_t)KK * PP];       // (K, P) column-major sm2

// ------------------------- K0: transpose Ws_out -------------------------
__global__ void k0_transpose(const float* __restrict__ WsOut) {
    int j = blockIdx.x;          // 0..189
    int t = threadIdx.x;         // 0..191
    g_wsT[j * 192 + t] = (t < KK) ? WsOut[t * DE + j] : 0.0f;
}

// ------------------------- K1: per-permutation vec rows -------------------------
__global__ void k1_vec(const float* __restrict__ matrix,
                       const float* __restrict__ WsIn,
                       const float* __restrict__ WdIn) {
    __shared__ float mS[DIMN * NPTS];      // 90
    __shared__ float projS[DIMN][RESTN];   // 3x27
    __shared__ float gramS[9];

    const int p = blockIdx.x;
    const int t = threadIdx.x;             // 0..191

    // decode lexicographic permutation p -> (a,b,c)
    int a  = p / 812;                // 812 = 29*28
    int r  = p - a * 812;
    int bi = r / 28;
    int ci = r - bi * 28;
    int b  = bi + (bi >= a);
    int e0 = min(a, b), e1 = max(a, b);
    int c  = ci + (ci >= e0);
    c += (c >= e1);

    // sorted excluded triple for rest[]
    int s0 = min(a, min(b, c));
    int s2 = max(a, max(b, c));
    int s1 = a + b + c - s0 - s2;

    if (t < DIMN * NPTS) mS[t] = matrix[t];
    __syncthreads();

    if (t < DIMN * RESTN) {
        int i = t / RESTN, m = t - i * RESTN;
        int rm = m + (m >= s0); rm += (rm >= s1); rm += (rm >= s2);
        int ci_ = (i == 0) ? a : ((i == 1) ? b : c);
        projS[i][m] = mS[ci_] * mS[rm]
                    + mS[NPTS + ci_] * mS[NPTS + rm]
                    + mS[2 * NPTS + ci_] * mS[2 * NPTS + rm];
    } else if (t < DIMN * RESTN + 9) {
        int q = t - DIMN * RESTN;
        int i = q / 3, j = q - 3 * i;
        int ci_ = (i == 0) ? a : ((i == 1) ? b : c);
        int cj_ = (j == 0) ? a : ((j == 1) ? b : c);
        gramS[q] = mS[ci_] * mS[cj_]
                 + mS[NPTS + ci_] * mS[NPTS + cj_]
                 + mS[2 * NPTS + ci_] * mS[2 * NPTS + cj_];
    }
    __syncthreads();

    float* vrow = g_vec + (size_t)p * DE;
    if (t < 9) vrow[t] = gramS[t];

    if (t < KK) {
        const int k = t;
        const float w0 = WsIn[k * 3 + 0];
        const float w1 = WsIn[k * 3 + 1];
        const float w2 = WsIn[k * 3 + 2];

        float v[32];
#pragma unroll
        for (int m = 0; m < RESTN; ++m)
            v[m] = fmaf(projS[2][m], w2, fmaf(projS[1][m], w1, projS[0][m] * w0));
        const float INF = __int_as_float(0x7f800000);
#pragma unroll
        for (int m = RESTN; m < 32; ++m) v[m] = INF;

        // fully-unrolled 32-element bitonic sort (ascending), stays in registers
#pragma unroll
        for (int size = 2; size <= 32; size <<= 1) {
#pragma unroll
            for (int stride = size >> 1; stride > 0; stride >>= 1) {
#pragma unroll
                for (int i = 0; i < 32; ++i) {
                    int j = i ^ stride;
                    if (j > i) {
                        bool up = ((i & size) == 0);
                        float x = v[i], y = v[j];
                        float lo = fminf(x, y), hi = fmaxf(x, y);
                        v[i] = up ? lo : hi;
                        v[j] = up ? hi : lo;
                    }
                }
            }
        }

        float e = 0.0f;
        const float* wd = WdIn + k * RESTN;
#pragma unroll
        for (int m = 0; m < RESTN; ++m) e = fmaf(wd[m], v[m], e);
        vrow[9 + k] = e;
    }
}

// ------------------------- K2: sm2T[k][p] = vec[p] . Ws_out[k] -------------------------
#define TP 64
#define JC 19
__global__ void k2_gemm() {
    __shared__ __align__(16) float vS[JC][TP];    // [j][p]
    __shared__ __align__(16) float wS[JC][192];   // [j][k]

    const int p0 = blockIdx.x * TP;
    const int t  = threadIdx.x;         // 256
    const int pt = t & 15;              // 16 p-threads
    const int kt = t >> 4;              // 16 k-threads

    float acc[4][12];
#pragma unroll
    for (int r0 = 0; r0 < 4; ++r0)
#pragma unroll
        for (int cc = 0; cc < 12; ++cc) acc[r0][cc] = 0.0f;

    for (int j0 = 0; j0 < DE; j0 += JC) {
        __syncthreads();
        for (int idx = t; idx < JC * TP; idx += 256) {
            int row = idx >> 6;              // /64
            int col = idx & 63;
            int p = p0 + col;
            vS[row][col] = (p < PP) ? g_vec[(size_t)p * DE + (j0 + row)] : 0.0f;
        }
        for (int idx = t; idx < JC * 192; idx += 256) {
            int row = idx / 192;
            int col = idx - row * 192;
            wS[row][col] = g_wsT[(j0 + row) * 192 + col];
        }
        __syncthreads();

#pragma unroll
        for (int jj = 0; jj < JC; ++jj) {
            float4 rv = *reinterpret_cast<const float4*>(&vS[jj][pt * 4]);
            float rr[4] = {rv.x, rv.y, rv.z, rv.w};
            const float4* wrow = reinterpret_cast<const float4*>(&wS[jj][0]);
            float4 wa = wrow[kt * 3 + 0];
            float4 wb = wrow[kt * 3 + 1];
            float4 wc = wrow[kt * 3 + 2];
            float w[12] = {wa.x, wa.y, wa.z, wa.w,
                           wb.x, wb.y, wb.z, wb.w,
                           wc.x, wc.y, wc.z, wc.w};
#pragma unroll
            for (int cc = 0; cc < 12; ++cc) {
#pragma unroll
                for (int r0 = 0; r0 < 4; ++r0)
                    acc[r0][cc] = fmaf(rr[r0], w[cc], acc[r0][cc]);
            }
        }
    }

    const bool full = (p0 + TP <= PP);
#pragma unroll
    for (int cc = 0; cc < 12; ++cc) {
        int k = kt * 12 + cc;
        if (k >= KK) continue;
        size_t base = (size_t)k * PP + p0 + pt * 4;
        if (full) {
            float4 val = make_float4(acc[0][cc], acc[1][cc], acc[2][cc], acc[3][cc]);
            *reinterpret_cast<float4*>(&g_sm2T[base]) = val;
        } else {
#pragma unroll
            for (int r0 = 0; r0 < 4; ++r0) {
                int p = p0 + pt * 4 + r0;
                if (p < PP) g_sm2T[(size_t)k * PP + p] = acc[r0][cc];
            }
        }
    }
}

// ------------------------- K3: per-k smem bitonic sort + weighted reduce ----------------
__global__ void k3_sortdot(const float* __restrict__ WdOut, float* __restrict__ out) {
    extern __shared__ float s[];               // SORT_V floats
    __shared__ float red[32];
    const int k = blockIdx.x;
    const int t = threadIdx.x;                 // 1024
    const float INF = __int_as_float(0x7f800000);

    const float* col = g_sm2T + (size_t)k * PP;
    for (int i = t; i < SORT_V; i += 1024)
        s[i] = (i < PP) ? col[i] : INF;
    __syncthreads();

    for (int size = 2; size <= SORT_V; size <<= 1) {
        for (int stride = size >> 1; stride > 0; stride >>= 1) {
            for (int u = t; u < (SORT_V / 2); u += 1024) {
                int pos = 2 * u - (u & (stride - 1));
                int q   = pos + stride;
                float x = s[pos], y = s[q];
                bool up = ((pos & size) == 0);
                float lo = fminf(x, y), hi = fmaxf(x, y);
                s[pos] = up ? lo : hi;
                s[q]   = up ? hi : lo;
            }
            __syncthreads();
        }
    }

    float acc = 0.0f;
    const float* wrow = WdOut + (size_t)k * PP;
    for (int i = t; i < PP; i += 1024)
        acc = fmaf(wrow[i], s[i], acc);
#pragma unroll
    for (int o = 16; o > 0; o >>= 1)
        acc += __shfl_down_sync(0xffffffffu, acc, o);
    if ((t & 31) == 0) red[t >> 5] = acc;
    __syncthreads();
    if (t < 32) {
        float x = red[t];
#pragma unroll
        for (int o = 16; o > 0; o >>= 1)
            x += __shfl_down_sync(0xffffffffu, x, o);
        if (t == 0) out[k] = x;
    }
}

// ------------------------- launch -------------------------
extern "C" void kernel_launch(void* const* d_in, const int* in_sizes, int n_in,
                              void* d_out, int out_size) {
    const float* matrix = (const float*)d_in[0];
    const float* WsIn   = (const float*)d_in[1];
    const float* WdIn   = (const float*)d_in[2];
    const float* WsOut  = (const float*)d_in[3];
    const float* WdOut  = (const float*)d_in[4];
    float* out = (float*)d_out;

    cudaFuncSetAttribute(k3_sortdot, cudaFuncAttributeMaxDynamicSharedMemorySize,
                         SORT_V * (int)sizeof(float));

    k0_transpose<<<DE, 192>>>(WsOut);
    k1_vec<<<PP, 192>>>(matrix, WsIn, WdIn);
    k2_gemm<<<(PP + TP - 1) / TP, 256>>>();
    k3_sortdot<<<KK, 1024, SORT_V * sizeof(float)>>>(WdOut, out);
}